// round 10
// baseline (speedup 1.0000x reference)
#include <cuda_runtime.h>
#include <cstddef>

// enc[t, b, d] = (clip(int(scaling[d]*|x[b]-center[d]|), 0, T-1) == t)
// Output [T=64, B=131072, n=16] fp32 = 512 MB -> pure HBM-store-bound.
// One thread per b per 16-t chunk: t_spike[16] in registers, then per t
// emit 4x float4 streaming stores (64 B contiguous per thread, 2 KB per warp
// per t -> perfectly coalesced STG.128).

#define NDIM   16
#define TCHUNK 16

template <bool FULL>
__global__ void __launch_bounds__(256)
enc16_kernel(const float* __restrict__ x,
             const float* __restrict__ center,
             const float* __restrict__ scaling,
             float* __restrict__ out,
             int B, int T)
{
    int b = blockIdx.x * 256 + threadIdx.x;
    if (b >= B) return;

    const float xv = __ldg(&x[b]);

    int ts[NDIM];
#pragma unroll
    for (int d = 0; d < NDIM; d++) {
        float v = __ldg(&scaling[d]) * fabsf(xv - __ldg(&center[d]));
        int t = (int)v;                    // v >= 0 -> trunc == floor; lower clip free
        ts[d] = (t < T - 1) ? t : (T - 1); // upper clip
    }

    const int t0 = blockIdx.y * TCHUNK;
    float4* __restrict__ base = reinterpret_cast<float4*>(out) + (size_t)b * (NDIM / 4);
    const size_t strideT = (size_t)B * (NDIM / 4);

#pragma unroll
    for (int tt = 0; tt < TCHUNK; tt++) {
        const int t = t0 + tt;
        if (!FULL) { if (t >= T) break; }
        float4 v[4];
#pragma unroll
        for (int g = 0; g < 4; g++) {
            v[g].x = (ts[4 * g + 0] == t) ? 1.0f : 0.0f;
            v[g].y = (ts[4 * g + 1] == t) ? 1.0f : 0.0f;
            v[g].z = (ts[4 * g + 2] == t) ? 1.0f : 0.0f;
            v[g].w = (ts[4 * g + 3] == t) ? 1.0f : 0.0f;
        }
        float4* __restrict__ p = base + (size_t)t * strideT;
#pragma unroll
        for (int g = 0; g < 4; g++) __stcs(p + g, v[g]);
    }
}

// Fallback for unexpected shapes (n != 16): one thread per output element.
__global__ void enc_generic_kernel(const float* __restrict__ x,
                                   const float* __restrict__ center,
                                   const float* __restrict__ scaling,
                                   float* __restrict__ out,
                                   int B, int N, int T)
{
    long long total = (long long)T * B * N;
    long long idx = blockIdx.x * (long long)blockDim.x + threadIdx.x;
    long long stride = (long long)gridDim.x * blockDim.x;
    for (; idx < total; idx += stride) {
        int d = (int)(idx % N);
        long long r = idx / N;
        int b = (int)(r % B);
        int t = (int)(r / B);
        float v = scaling[d] * fabsf(x[b] - center[d]);
        int tsv = (int)v;
        if (tsv > T - 1) tsv = T - 1;
        out[idx] = (tsv == t) ? 1.0f : 0.0f;
    }
}

extern "C" void kernel_launch(void* const* d_in, const int* in_sizes, int n_in,
                              void* d_out, int out_size)
{
    const float* x       = (const float*)d_in[0];
    const float* center  = (const float*)d_in[1];
    const float* scaling = (const float*)d_in[2];
    float* out = (float*)d_out;

    const int B = in_sizes[0];
    const int N = in_sizes[1];
    // time_steps lives on-device (d_in[3]); derive T from out_size instead of
    // a sync copy (banned under graph capture).
    long long T_ll = (B > 0 && N > 0) ? ((long long)out_size / ((long long)B * N)) : 0;
    const int T = (int)T_ll;

    if (N == NDIM && T > 0 && (long long)B * N * T == (long long)out_size) {
        dim3 grid((B + 255) / 256, (T + TCHUNK - 1) / TCHUNK);
        if (T % TCHUNK == 0)
            enc16_kernel<true><<<grid, 256>>>(x, center, scaling, out, B, T);
        else
            enc16_kernel<false><<<grid, 256>>>(x, center, scaling, out, B, T);
    } else {
        long long total = (long long)out_size;
        int threads = 256;
        long long blocks_ll = (total + threads - 1) / threads;
        int blocks = (blocks_ll > 65535 * 32LL) ? 65535 * 32 : (int)blocks_ll;
        if (blocks < 1) blocks = 1;
        enc_generic_kernel<<<blocks, threads>>>(x, center, scaling, out, B, N, T);
    }
}

// round 11
// speedup vs baseline: 1.1101x; 1.1101x over previous
#include <cuda_runtime.h>
#include <cstddef>

// enc[t, b, d] = (clip(int(scaling[d]*|x[b]-center[d]|), 0, T-1) == t)
// Output [T=64, B=131072, n=16] fp32 = 512 MB.
// R10 ncu: L1TEX 78.4% (max unit), DRAM only 30.5% -> store-path-bound in
// L1tex, ~47 cyc/STG.128 vs 12 expected. Theory: __stcs (.cs) takes a slow
// per-sector path on sm_103a. This round: identical kernel, plain .wb
// float4 stores instead of __stcs.

#define NDIM   16
#define TCHUNK 16

template <bool FULL>
__global__ void __launch_bounds__(256)
enc16_kernel(const float* __restrict__ x,
             const float* __restrict__ center,
             const float* __restrict__ scaling,
             float* __restrict__ out,
             int B, int T)
{
    int b = blockIdx.x * 256 + threadIdx.x;
    if (b >= B) return;

    const float xv = __ldg(&x[b]);

    int ts[NDIM];
#pragma unroll
    for (int d = 0; d < NDIM; d++) {
        float v = __ldg(&scaling[d]) * fabsf(xv - __ldg(&center[d]));
        int t = (int)v;                    // v >= 0 -> trunc == floor; lower clip free
        ts[d] = (t < T - 1) ? t : (T - 1); // upper clip
    }

    const int t0 = blockIdx.y * TCHUNK;
    float4* __restrict__ base = reinterpret_cast<float4*>(out) + (size_t)b * (NDIM / 4);
    const size_t strideT = (size_t)B * (NDIM / 4);

#pragma unroll
    for (int tt = 0; tt < TCHUNK; tt++) {
        const int t = t0 + tt;
        if (!FULL) { if (t >= T) break; }
        float4 v[4];
#pragma unroll
        for (int g = 0; g < 4; g++) {
            v[g].x = (ts[4 * g + 0] == t) ? 1.0f : 0.0f;
            v[g].y = (ts[4 * g + 1] == t) ? 1.0f : 0.0f;
            v[g].z = (ts[4 * g + 2] == t) ? 1.0f : 0.0f;
            v[g].w = (ts[4 * g + 3] == t) ? 1.0f : 0.0f;
        }
        float4* __restrict__ p = base + (size_t)t * strideT;
#pragma unroll
        for (int g = 0; g < 4; g++) p[g] = v[g];   // default .wb STG.E.128
    }
}

// Fallback for unexpected shapes (n != 16): one thread per output element.
__global__ void enc_generic_kernel(const float* __restrict__ x,
                                   const float* __restrict__ center,
                                   const float* __restrict__ scaling,
                                   float* __restrict__ out,
                                   int B, int N, int T)
{
    long long total = (long long)T * B * N;
    long long idx = blockIdx.x * (long long)blockDim.x + threadIdx.x;
    long long stride = (long long)gridDim.x * blockDim.x;
    for (; idx < total; idx += stride) {
        int d = (int)(idx % N);
        long long r = idx / N;
        int b = (int)(r % B);
        int t = (int)(r / B);
        float v = scaling[d] * fabsf(x[b] - center[d]);
        int tsv = (int)v;
        if (tsv > T - 1) tsv = T - 1;
        out[idx] = (tsv == t) ? 1.0f : 0.0f;
    }
}

extern "C" void kernel_launch(void* const* d_in, const int* in_sizes, int n_in,
                              void* d_out, int out_size)
{
    const float* x       = (const float*)d_in[0];
    const float* center  = (const float*)d_in[1];
    const float* scaling = (const float*)d_in[2];
    float* out = (float*)d_out;

    const int B = in_sizes[0];
    const int N = in_sizes[1];
    // time_steps lives on-device (d_in[3]); derive T from out_size instead of
    // a sync copy (banned under graph capture).
    long long T_ll = (B > 0 && N > 0) ? ((long long)out_size / ((long long)B * N)) : 0;
    const int T = (int)T_ll;

    if (N == NDIM && T > 0 && (long long)B * N * T == (long long)out_size) {
        dim3 grid((B + 255) / 256, (T + TCHUNK - 1) / TCHUNK);
        if (T % TCHUNK == 0)
            enc16_kernel<true><<<grid, 256>>>(x, center, scaling, out, B, T);
        else
            enc16_kernel<false><<<grid, 256>>>(x, center, scaling, out, B, T);
    } else {
        long long total = (long long)out_size;
        int threads = 256;
        long long blocks_ll = (total + threads - 1) / threads;
        int blocks = (blocks_ll > 65535 * 32LL) ? 65535 * 32 : (int)blocks_ll;
        if (blocks < 1) blocks = 1;
        enc_generic_kernel<<<blocks, threads>>>(x, center, scaling, out, B, N, T);
    }
}